// round 10
// baseline (speedup 1.0000x reference)
#include <cuda_runtime.h>
#include <math.h>

#define TT   1460
#define GG   5000
#define TS   30              // timesteps per smem tile (2 x 15-chunk)
#define NT   49              // ceil(1460/30)
#define CH   15              // UH length = ring period
#define CPW  4               // cells per warp (lanes 4-31 duplicate lane&3)
#define WPB  4               // warps per block -> one per SMSP
#define CPB  16              // cells per block
#define RW   12              // floats per row per warp (CPW * 3)

// ---- packed f32x2 + approx transcendental helpers -----------------------------
#define PACK2(d, lo, hi)   asm("mov.b64 %0, {%1, %2};" : "=l"(d) : "f"(lo), "f"(hi))
#define UNPACK2(lo, hi, d) asm("mov.b64 {%0, %1}, %2;" : "=f"(lo), "=f"(hi) : "l"(d))
#define FMA2(d, a, b, c)   asm("fma.rn.f32x2 %0, %1, %2, %3;" : "=l"(d) : "l"(a), "l"(b), "l"(c))

__device__ __forceinline__ float lg2a(float x) { float r; asm("lg2.approx.f32 %0, %1;" : "=f"(r) : "f"(x)); return r; }
__device__ __forceinline__ float ex2a(float x) { float r; asm("ex2.approx.f32 %0, %1;" : "=f"(r) : "f"(x)); return r; }

__device__ __forceinline__ void cp_async16(void* sm, const void* gm) {
    unsigned a = (unsigned)__cvta_generic_to_shared(sm);
    asm volatile("cp.async.cg.shared.global [%0], [%1], 16;\n" :: "r"(a), "l"(gm));
}
__device__ __forceinline__ void cp_commit() { asm volatile("cp.async.commit_group;\n" ::: "memory"); }
__device__ __forceinline__ void cp_wait1()  { asm volatile("cp.async.wait_group 1;\n" ::: "memory"); }
__device__ __forceinline__ void cp_wait0()  { asm volatile("cp.async.wait_group 0;\n" ::: "memory"); }

__global__ __launch_bounds__(128)
void hmets_kernel(const float* __restrict__ x,
                  const float* __restrict__ par,
                  float* __restrict__ out)
{
    // per-warp private double-buffered forcing tiles (no cross-warp sharing)
    __shared__ __align__(16) float smAll[WPB][2][TS * RW];   // 11520 B

    const int tid  = threadIdx.x;
    const int wid  = tid >> 5;
    const int lane = tid & 31;
    const int li   = lane & 3;                    // cell slot within warp
    const int gw0  = blockIdx.x * CPB + wid * CPW;
    const bool wact = (gw0 < GG);                 // GG % CPW == 0 -> whole warp valid/invalid
    const int g    = gw0 + li;

    float (*smw)[TS * RW] = smAll[wid];

    // ---------------- parameters: only the last timestep row is live ----------------
    const int gcl = wact ? (g < GG ? g : GG - 1) : 0;
    const float* pr = par + ((size_t)(TT - 1) * GG + gcl) * 20;
    float s[20];
#pragma unroll
    for (int i = 0; i < 20; i++) {
        float v = __ldg(pr + i);
        s[i] = 1.0f / (1.0f + expf(-v));
    }
    const float ddf_min = 20.0f * s[0];
    const float ddf_sum = ddf_min + 20.0f * s[1];
    const float Tbm     = -2.0f + 5.0f * s[2];
    const float Kcum    = 0.01f + 0.19f * s[3];
    const float fcmin   = 0.1f * s[4];
    const float fc_sum  = fcmin + 0.01f + 0.24f * s[5];
    const float Ccum    = 0.005f + 0.045f * s[6];
    const float Tbf     = -5.0f + 7.0f * s[7];
    const float Kf      = 5.0f * s[8];
    const float efe     = s[9];
    const float ETe     = 3.0f * s[10];
    const float cRun    = s[11];
    const float cV2P    = 1e-5f + (0.02f - 1e-5f) * s[12];
    const float cVad    = 0.1f * s[13];
    const float cPh     = 1e-5f + (0.01f - 1e-5f) * s[14];
    const float Vmax    = 0.001f + (500.0f - 0.001f) * s[15];
    const float invVmax = 1.0f / Vmax;
    const float dmK  = ddf_min * Kcum;       // ddf = fma(dmK, C, ddf_min)
    const float fcC  = fc_sum * Ccum;        // wrf = fma(-fcC, C, fc_sum)
    const float cVb  = 1.0f - cVad - cV2P;   // V1 = fma(cVb, V, infil) - ht1

    // ---------------- gamma unit hydrographs, packed (uh1[l], uh2[l]) ---------------
    unsigned long long uhp[CH];
    {
        float a1 = 0.3f  + (20.0f - 0.3f)  * s[16];
        float b1 = 0.01f + (5.0f  - 0.01f) * s[17];
        float a2 = 0.5f  + (13.0f - 0.5f)  * s[18];
        float b2 = 0.15f + (1.5f  - 0.15f) * s[19];
        float i1 = 1.0f / b1, i2 = 1.0f / b2;
        float w1[CH], w2[CH];
        float n1 = 0.f, n2 = 0.f;
#pragma unroll
        for (int l = 0; l < CH; l++) {
            float t  = (float)l + 0.5f;
            w1[l] = powf(t, a1 - 1.0f) * expf(-t * i1);
            w2[l] = powf(t, a2 - 1.0f) * expf(-t * i2);
            n1 += w1[l]; n2 += w2[l];
        }
        n1 = 1.0f / n1; n2 = 1.0f / n2;
#pragma unroll
        for (int l = 0; l < CH; l++) PACK2(uhp[l], w1[l] * n1, w2[l] * n2);
    }

    // ---------------- per-warp tile prefetch (cp.async, zero-padded) ----------------
    // cells gw0..gw0+3 are 12 contiguous floats (48 B, 16B-aligned since gw0 % 4 == 0)
    auto prefetch = [&](int k) {
        float* dst = smw[k & 1];
        int t0 = k * TS;
        for (int j = lane; j < TS * 3; j += 32) {      // 3 float4 per row
            int row = j / 3, c = j - row * 3;
            if (wact && (t0 + row) < TT) {
                const float* gp = x + (size_t)(t0 + row) * (GG * 3) + gw0 * 3 + c * 4;
                cp_async16(dst + row * RW + c * 4, gp);
            } else {
                float4 z = {0.f, 0.f, 0.f, 0.f};
                *(float4*)(dst + row * RW + c * 4) = z;
            }
        }
        cp_commit();
    };

    // ---------------- state + packed conv history (circular, unroll-aligned) --------
    float S = 1e-5f, W = 1e-5f, C = 1e-5f, P = 1e-5f;
    float V = 0.5f * Vmax;
    unsigned long long hpk[CH];
#pragma unroll
    for (int l = 0; l < CH; l++) hpk[l] = 0ull;

    const bool wr_act = wact && (lane < CPW);
    float* op = out + g;          // advances by GG per step

    prefetch(0);
    for (int k = 0; k < NT; k++) {
        const int t0 = k * TS;
        if (k + 1 < NT) { prefetch(k + 1); cp_wait1(); }
        else            { cp_wait0(); }
        __syncwarp();
        const float* sb = smw[k & 1];

#pragma unroll 1
        for (int c2 = 0; c2 < 2; c2++) {        // two aligned 15-chunks per tile
            const float* rb = sb + c2 * CH * RW + li * 3;
            const int tb = t0 + c2 * CH;
#pragma unroll
            for (int u = 0; u < CH; u++) {
                float Pp = rb[u * RW + 0];
                float Tt = rb[u * RW + 1];
                float PE = rb[u * RW + 2];

                // forcing-derived (all off the state recurrence)
                float rain = (Tt >= 0.0f) ? Pp : 0.0f;
                float snow = Pp - rain;
                float base = fmaxf(Tbf - Tt, 1e-5f);
                float potf = Kf * ex2a(efe * lg2a(base));
                float dtp  = fmaxf(Tt - Tbm, 0.0f);
                float RET  = ETe * PE;

                // snowpack
                float fr = fminf(potf, W);
                W -= fr;
                S += fr;
                float ddf  = fminf(fmaf(dmK, C, ddf_min), ddf_sum);
                float S1   = S + snow;
                float melt = fminf(ddf * dtp, S1);
                S = S1 - melt;
                float Ct = C + melt;
                C = (S > 1e-5f) ? Ct : 0.0f;

                // retention (select -> min identity, exact)
                float wrf  = fmaxf(fmaf(-fcC, C, fc_sum), fcmin);
                float wr   = wrf * S;
                float wtmp = (W + rain) + melt;
                float wa   = fmaxf(wtmp - wr, 0.0f);
                W = fminf(wtmp, wr);

                // vadose / phreatic (overflow clamp -> min identity, exact)
                float ratio = V * invVmax;
                float cr    = cRun * ratio;
                float cr2   = cr * ratio;
                float ht0   = cr * wa;
                float infil = fmaxf((wa - RET) - ht0, 0.0f);
                float ht1   = cr2 * infil;
                float ht2   = cVad * V;
                float v2p   = cV2P * V;
                float V1    = fmaf(cVb, V, infil) - ht1;
                V = fminf(V1, Vmax);
                ht1 += V1 - V;
                float Pp1 = P + v2p;
                float ht3 = cPh * Pp1;
                P = Pp1 - ht3;

                // 15-tap dual UH conv: two packed FFMA2 accumulator chains
                PACK2(hpk[u], ht0, ht1);
                unsigned long long qp0 = 0ull, qp1 = 0ull;
#pragma unroll
                for (int l = 0; l < 8; l++)
                    FMA2(qp0, uhp[l], hpk[(u - l + CH) % CH], qp0);
#pragma unroll
                for (int l = 8; l < CH; l++)
                    FMA2(qp1, uhp[l], hpk[(u - l + CH) % CH], qp1);
                float qa, qb, qc, qd;
                UNPACK2(qa, qb, qp0);
                UNPACK2(qc, qd, qp1);
                float q = ((ht2 + ht3) + (qa + qb)) + (qc + qd);

                if (wr_act && (tb + u) < TT) *op = q;
                op += GG;
            }
        }
        __syncwarp();
    }
}

extern "C" void kernel_launch(void* const* d_in, const int* in_sizes, int n_in,
                              void* d_out, int out_size)
{
    (void)in_sizes; (void)n_in; (void)out_size;
    const float* x   = (const float*)d_in[0];   // x_phy  [1460, 5000, 3]
    const float* par = (const float*)d_in[1];   // params [1460, 5000, 20]
    float* out = (float*)d_out;                 // Q      [1460, 5000]
    hmets_kernel<<<(GG + CPB - 1) / CPB, WPB * 32>>>(x, par, out);
}

// round 11
// speedup vs baseline: 1.2298x; 1.2298x over previous
#include <cuda_runtime.h>
#include <math.h>

#define TT   1460
#define GG   5000
#define TS   30              // timesteps per smem tile (2 x 15-chunk)
#define NT   49              // ceil(1460/30)
#define CH   15              // UH length = ring period
#define CPW  4               // cells per warp (lanes 4-31 duplicate lane&3)
#define WPB  4               // warps per block -> one per SMSP
#define CPB  16              // cells per block
#define RW   12              // floats per row per warp (CPW * 3)

// ---- packed f32x2 + approx transcendental helpers -----------------------------
#define PACK2(d, lo, hi)   asm("mov.b64 %0, {%1, %2};" : "=l"(d) : "f"(lo), "f"(hi))
#define UNPACK2(lo, hi, d) asm("mov.b64 {%0, %1}, %2;" : "=f"(lo), "=f"(hi) : "l"(d))
#define FMA2(d, a, b, c)   asm("fma.rn.f32x2 %0, %1, %2, %3;" : "=l"(d) : "l"(a), "l"(b), "l"(c))

__device__ __forceinline__ float lg2a(float x) { float r; asm("lg2.approx.f32 %0, %1;" : "=f"(r) : "f"(x)); return r; }
__device__ __forceinline__ float ex2a(float x) { float r; asm("ex2.approx.f32 %0, %1;" : "=f"(r) : "f"(x)); return r; }

__device__ __forceinline__ void cp_async16(void* sm, const void* gm) {
    unsigned a = (unsigned)__cvta_generic_to_shared(sm);
    asm volatile("cp.async.cg.shared.global [%0], [%1], 16;\n" :: "r"(a), "l"(gm));
}
__device__ __forceinline__ void cp_commit() { asm volatile("cp.async.commit_group;\n" ::: "memory"); }
__device__ __forceinline__ void cp_wait1()  { asm volatile("cp.async.wait_group 1;\n" ::: "memory"); }
__device__ __forceinline__ void cp_wait0()  { asm volatile("cp.async.wait_group 0;\n" ::: "memory"); }

__global__ __launch_bounds__(128, 1)      // <-- the fix: allow ~255 regs/thread, no spills
void hmets_kernel(const float* __restrict__ x,
                  const float* __restrict__ par,
                  float* __restrict__ out)
{
    // per-warp private double-buffered forcing tiles (no cross-warp sharing)
    __shared__ __align__(16) float smAll[WPB][2][TS * RW];   // 11520 B

    const int tid  = threadIdx.x;
    const int wid  = tid >> 5;
    const int lane = tid & 31;
    const int li   = lane & 3;                    // cell slot within warp
    const int gw0  = blockIdx.x * CPB + wid * CPW;
    const bool wact = (gw0 < GG);                 // GG % CPW == 0 -> whole warp valid/invalid
    const int g    = gw0 + li;

    float (*smw)[TS * RW] = smAll[wid];

    // ---------------- parameters: only the last timestep row is live ----------------
    const int gcl = wact ? (g < GG ? g : GG - 1) : 0;
    const float* pr = par + ((size_t)(TT - 1) * GG + gcl) * 20;
    float s[20];
#pragma unroll
    for (int i = 0; i < 20; i++) {
        float v = __ldg(pr + i);
        s[i] = 1.0f / (1.0f + expf(-v));
    }
    const float ddf_min = 20.0f * s[0];
    const float ddf_sum = ddf_min + 20.0f * s[1];
    const float Tbm     = -2.0f + 5.0f * s[2];
    const float Kcum    = 0.01f + 0.19f * s[3];
    const float fcmin   = 0.1f * s[4];
    const float fc_sum  = fcmin + 0.01f + 0.24f * s[5];
    const float Ccum    = 0.005f + 0.045f * s[6];
    const float Tbf     = -5.0f + 7.0f * s[7];
    const float Kf      = 5.0f * s[8];
    const float efe     = s[9];
    const float ETe     = 3.0f * s[10];
    const float cRun    = s[11];
    const float cV2P    = 1e-5f + (0.02f - 1e-5f) * s[12];
    const float cVad    = 0.1f * s[13];
    const float cPh     = 1e-5f + (0.01f - 1e-5f) * s[14];
    const float Vmax    = 0.001f + (500.0f - 0.001f) * s[15];
    const float invVmax = 1.0f / Vmax;
    const float dmK  = ddf_min * Kcum;       // ddf = fma(dmK, C, ddf_min)
    const float fcC  = fc_sum * Ccum;        // wrf = fma(-fcC, C, fc_sum)
    const float cVb  = 1.0f - cVad - cV2P;   // V1 = fma(cVb, V, infil) - ht1

    // ---------------- gamma unit hydrographs, packed (uh1[l], uh2[l]) ---------------
    unsigned long long uhp[CH];
    {
        float a1 = 0.3f  + (20.0f - 0.3f)  * s[16];
        float b1 = 0.01f + (5.0f  - 0.01f) * s[17];
        float a2 = 0.5f  + (13.0f - 0.5f)  * s[18];
        float b2 = 0.15f + (1.5f  - 0.15f) * s[19];
        float i1 = 1.0f / b1, i2 = 1.0f / b2;
        float w1[CH], w2[CH];
        float n1 = 0.f, n2 = 0.f;
#pragma unroll
        for (int l = 0; l < CH; l++) {
            float t  = (float)l + 0.5f;
            w1[l] = powf(t, a1 - 1.0f) * expf(-t * i1);
            w2[l] = powf(t, a2 - 1.0f) * expf(-t * i2);
            n1 += w1[l]; n2 += w2[l];
        }
        n1 = 1.0f / n1; n2 = 1.0f / n2;
#pragma unroll
        for (int l = 0; l < CH; l++) PACK2(uhp[l], w1[l] * n1, w2[l] * n2);
    }

    // ---------------- per-warp tile prefetch (cp.async, zero-padded) ----------------
    // cells gw0..gw0+3 are 12 contiguous floats (48 B, 16B-aligned since gw0 % 4 == 0)
    auto prefetch = [&](int k) {
        float* dst = smw[k & 1];
        int t0 = k * TS;
        for (int j = lane; j < TS * 3; j += 32) {      // 3 float4 per row
            int row = j / 3, c = j - row * 3;
            if (wact && (t0 + row) < TT) {
                const float* gp = x + (size_t)(t0 + row) * (GG * 3) + gw0 * 3 + c * 4;
                cp_async16(dst + row * RW + c * 4, gp);
            } else {
                float4 z = {0.f, 0.f, 0.f, 0.f};
                *(float4*)(dst + row * RW + c * 4) = z;
            }
        }
        cp_commit();
    };

    // ---------------- state + packed conv history (circular, unroll-aligned) --------
    float S = 1e-5f, W = 1e-5f, C = 1e-5f, P = 1e-5f;
    float V = 0.5f * Vmax;
    unsigned long long hpk[CH];
#pragma unroll
    for (int l = 0; l < CH; l++) hpk[l] = 0ull;

    const bool wr_act = wact && (lane < CPW);
    float* op = out + g;          // advances by GG per step

    prefetch(0);
    for (int k = 0; k < NT; k++) {
        const int t0 = k * TS;
        if (k + 1 < NT) { prefetch(k + 1); cp_wait1(); }
        else            { cp_wait0(); }
        __syncwarp();
        const float* sb = smw[k & 1];

#pragma unroll 1
        for (int c2 = 0; c2 < 2; c2++) {        // two aligned 15-chunks per tile
            const float* rb = sb + c2 * CH * RW + li * 3;
            const int tb = t0 + c2 * CH;
#pragma unroll
            for (int u = 0; u < CH; u++) {
                float Pp = rb[u * RW + 0];
                float Tt = rb[u * RW + 1];
                float PE = rb[u * RW + 2];

                // forcing-derived (all off the state recurrence)
                float rain = (Tt >= 0.0f) ? Pp : 0.0f;
                float snow = Pp - rain;
                float base = fmaxf(Tbf - Tt, 1e-5f);
                float potf = Kf * ex2a(efe * lg2a(base));
                float dtp  = fmaxf(Tt - Tbm, 0.0f);
                float RET  = ETe * PE;

                // snowpack
                float fr = fminf(potf, W);
                W -= fr;
                S += fr;
                float ddf  = fminf(fmaf(dmK, C, ddf_min), ddf_sum);
                float S1   = S + snow;
                float melt = fminf(ddf * dtp, S1);
                S = S1 - melt;
                float Ct = C + melt;
                C = (S > 1e-5f) ? Ct : 0.0f;

                // retention (select -> min identity, exact)
                float wrf  = fmaxf(fmaf(-fcC, C, fc_sum), fcmin);
                float wr   = wrf * S;
                float wtmp = (W + rain) + melt;
                float wa   = fmaxf(wtmp - wr, 0.0f);
                W = fminf(wtmp, wr);

                // vadose / phreatic (overflow clamp -> min identity, exact)
                float ratio = V * invVmax;
                float cr    = cRun * ratio;
                float cr2   = cr * ratio;
                float ht0   = cr * wa;
                float infil = fmaxf((wa - RET) - ht0, 0.0f);
                float ht1   = cr2 * infil;
                float ht2   = cVad * V;
                float v2p   = cV2P * V;
                float V1    = fmaf(cVb, V, infil) - ht1;
                V = fminf(V1, Vmax);
                ht1 += V1 - V;
                float Pp1 = P + v2p;
                float ht3 = cPh * Pp1;
                P = Pp1 - ht3;

                // 15-tap dual UH conv: two packed FFMA2 accumulator chains
                PACK2(hpk[u], ht0, ht1);
                unsigned long long qp0 = 0ull, qp1 = 0ull;
#pragma unroll
                for (int l = 0; l < 8; l++)
                    FMA2(qp0, uhp[l], hpk[(u - l + CH) % CH], qp0);
#pragma unroll
                for (int l = 8; l < CH; l++)
                    FMA2(qp1, uhp[l], hpk[(u - l + CH) % CH], qp1);
                float qa, qb, qc, qd;
                UNPACK2(qa, qb, qp0);
                UNPACK2(qc, qd, qp1);
                float q = ((ht2 + ht3) + (qa + qb)) + (qc + qd);

                if (wr_act && (tb + u) < TT) *op = q;
                op += GG;
            }
        }
        __syncwarp();
    }
}

extern "C" void kernel_launch(void* const* d_in, const int* in_sizes, int n_in,
                              void* d_out, int out_size)
{
    (void)in_sizes; (void)n_in; (void)out_size;
    const float* x   = (const float*)d_in[0];   // x_phy  [1460, 5000, 3]
    const float* par = (const float*)d_in[1];   // params [1460, 5000, 20]
    float* out = (float*)d_out;                 // Q      [1460, 5000]
    hmets_kernel<<<(GG + CPB - 1) / CPB, WPB * 32>>>(x, par, out);
}

// round 12
// speedup vs baseline: 2.5972x; 2.1119x over previous
#include <cuda_runtime.h>
#include <math.h>

#define TT   1460
#define GG   5000
#define TS   30              // timesteps per smem tile
#define NT   49              // ceil(1460/30)
#define CH   15              // UH length
#define CPW  4               // cells per warp (lanes 4-31 duplicate lane&3)
#define WPB  4               // warps per block -> one per SMSP
#define CPB  16              // cells per block
#define RW   12              // floats per row per warp (CPW * 3)
#define NSL  14              // conv t-slices
#define SLEN 105             // steps per conv slice (7 * 15)

// scratch: (ht0, ht1, gw, pad) per (t, g) -- 116.8 MB
__device__ float4 g_scr[(size_t)TT * GG];

// ---- packed f32x2 + approx transcendental helpers -----------------------------
#define PACK2(d, lo, hi)   asm("mov.b64 %0, {%1, %2};" : "=l"(d) : "f"(lo), "f"(hi))
#define UNPACK2(lo, hi, d) asm("mov.b64 {%0, %1}, %2;" : "=f"(lo), "=f"(hi) : "l"(d))
#define FMA2(d, a, b, c)   asm("fma.rn.f32x2 %0, %1, %2, %3;" : "=l"(d) : "l"(a), "l"(b), "l"(c))

__device__ __forceinline__ float lg2a(float x) { float r; asm("lg2.approx.f32 %0, %1;" : "=f"(r) : "f"(x)); return r; }
__device__ __forceinline__ float ex2a(float x) { float r; asm("ex2.approx.f32 %0, %1;" : "=f"(r) : "f"(x)); return r; }

__device__ __forceinline__ void cp_async16(void* sm, const void* gm) {
    unsigned a = (unsigned)__cvta_generic_to_shared(sm);
    asm volatile("cp.async.cg.shared.global [%0], [%1], 16;\n" :: "r"(a), "l"(gm));
}
__device__ __forceinline__ void cp_commit() { asm volatile("cp.async.commit_group;\n" ::: "memory"); }
__device__ __forceinline__ void cp_wait1()  { asm volatile("cp.async.wait_group 1;\n" ::: "memory"); }
__device__ __forceinline__ void cp_wait0()  { asm volatile("cp.async.wait_group 0;\n" ::: "memory"); }

// ============== Kernel A: warp-spread scan (spine only, no conv) ================
__global__ __launch_bounds__(128, 1)
void hmets_scan(const float* __restrict__ x,
                const float* __restrict__ par)
{
    __shared__ __align__(16) float smAll[WPB][2][TS * RW];   // 11520 B

    const int tid  = threadIdx.x;
    const int wid  = tid >> 5;
    const int lane = tid & 31;
    const int li   = lane & 3;                    // cell slot within warp
    const int gw0  = blockIdx.x * CPB + wid * CPW;
    const bool wact = (gw0 < GG);                 // GG % CPW == 0
    const int g    = gw0 + li;

    float (*smw)[TS * RW] = smAll[wid];

    // -------- per-cell physical parameters (last timestep row only) -----------------
    const int gcl = wact ? (g < GG ? g : GG - 1) : 0;
    const float* pr = par + ((size_t)(TT - 1) * GG + gcl) * 20;
    float s[16];
#pragma unroll
    for (int i = 0; i < 16; i++) {
        float v = __ldg(pr + i);
        s[i] = 1.0f / (1.0f + expf(-v));
    }
    const float ddf_min = 20.0f * s[0];
    const float ddf_sum = ddf_min + 20.0f * s[1];
    const float Tbm     = -2.0f + 5.0f * s[2];
    const float Kcum    = 0.01f + 0.19f * s[3];
    const float fcmin   = 0.1f * s[4];
    const float fc_sum  = fcmin + 0.01f + 0.24f * s[5];
    const float Ccum    = 0.005f + 0.045f * s[6];
    const float Tbf     = -5.0f + 7.0f * s[7];
    const float Kf      = 5.0f * s[8];
    const float efe     = s[9];
    const float ETe     = 3.0f * s[10];
    const float cRun    = s[11];
    const float cV2P    = 1e-5f + (0.02f - 1e-5f) * s[12];
    const float cVad    = 0.1f * s[13];
    const float cPh     = 1e-5f + (0.01f - 1e-5f) * s[14];
    const float Vmax    = 0.001f + (500.0f - 0.001f) * s[15];
    const float invVmax = 1.0f / Vmax;
    const float dmK  = ddf_min * Kcum;       // ddf = fma(dmK, C, ddf_min)
    const float fcC  = fc_sum * Ccum;        // wrf = fma(-fcC, C, fc_sum)
    const float cVb  = 1.0f - cVad - cV2P;   // V1 = fma(cVb, V, infil) - ht1

    // -------- per-warp tile prefetch (cp.async, zero-padded) ------------------------
    auto prefetch = [&](int k) {
        float* dst = smw[k & 1];
        int t0 = k * TS;
        for (int j = lane; j < TS * 3; j += 32) {      // 3 float4 per row
            int row = j / 3, c = j - row * 3;
            if (wact && (t0 + row) < TT) {
                const float* gp = x + (size_t)(t0 + row) * (GG * 3) + gw0 * 3 + c * 4;
                cp_async16(dst + row * RW + c * 4, gp);
            } else {
                float4 z = {0.f, 0.f, 0.f, 0.f};
                *(float4*)(dst + row * RW + c * 4) = z;
            }
        }
        cp_commit();
    };

    // -------- state -----------------------------------------------------------------
    float S = 1e-5f, W = 1e-5f, C = 1e-5f, P = 1e-5f;
    float V = 0.5f * Vmax;

    const bool wr_act = wact && (lane < CPW);
    float4* sp = g_scr + g;       // advances by GG per step

    prefetch(0);
    for (int k = 0; k < NT; k++) {
        const int t0 = k * TS;
        if (k + 1 < NT) { prefetch(k + 1); cp_wait1(); }
        else            { cp_wait0(); }
        __syncwarp();
        const float* sb = smw[k & 1];

#pragma unroll 1
        for (int c2 = 0; c2 < 2; c2++) {
            const float* rb = sb + c2 * CH * RW + li * 3;
            const int tb = t0 + c2 * CH;
#pragma unroll
            for (int u = 0; u < CH; u++) {
                float Pp = rb[u * RW + 0];
                float Tt = rb[u * RW + 1];
                float PE = rb[u * RW + 2];

                // forcing-derived (off the state recurrence)
                float rain = (Tt >= 0.0f) ? Pp : 0.0f;
                float snow = Pp - rain;
                float base = fmaxf(Tbf - Tt, 1e-5f);
                float potf = Kf * ex2a(efe * lg2a(base));
                float dtp  = fmaxf(Tt - Tbm, 0.0f);
                float RET  = ETe * PE;

                // snowpack
                float fr = fminf(potf, W);
                W -= fr;
                S += fr;
                float ddf  = fminf(fmaf(dmK, C, ddf_min), ddf_sum);
                float S1   = S + snow;
                float melt = fminf(ddf * dtp, S1);
                S = S1 - melt;
                float Ct = C + melt;
                C = (S > 1e-5f) ? Ct : 0.0f;

                // retention (select -> min identity, exact)
                float wrf  = fmaxf(fmaf(-fcC, C, fc_sum), fcmin);
                float wr   = wrf * S;
                float wtmp = (W + rain) + melt;
                float wa   = fmaxf(wtmp - wr, 0.0f);
                W = fminf(wtmp, wr);

                // vadose / phreatic (overflow clamp -> min identity, exact)
                float ratio = V * invVmax;
                float cr    = cRun * ratio;
                float cr2   = cr * ratio;
                float ht0   = cr * wa;
                float infil = fmaxf((wa - RET) - ht0, 0.0f);
                float ht1   = cr2 * infil;
                float ht2   = cVad * V;
                float v2p   = cV2P * V;
                float V1    = fmaf(cVb, V, infil) - ht1;
                V = fminf(V1, Vmax);
                ht1 += V1 - V;
                float Pp1 = P + v2p;
                float ht3 = cPh * Pp1;
                P = Pp1 - ht3;

                if (wr_act && (tb + u) < TT) {
                    float4 h; h.x = ht0; h.y = ht1; h.z = ht2 + ht3; h.w = 0.0f;
                    *sp = h;                       // one STG.128, coalesced x4
                }
                sp += GG;
            }
        }
        __syncwarp();
    }
}

// ============== Kernel B: dual gamma-UH conv (proven 27us, R8) ==================
__global__ __launch_bounds__(32, 16)
void hmets_conv(const float* __restrict__ par,
                float* __restrict__ out)
{
    const int lane = threadIdx.x;
    const int g    = blockIdx.x * 32 + lane;
    if (g >= GG) return;
    const int t0   = blockIdx.y * SLEN;

    // routing params (sigmoid of last row, cols 16..19)
    const float* pr = par + ((size_t)(TT - 1) * GG + g) * 20 + 16;
    float a1 = 0.3f  + (20.0f - 0.3f)  / (1.0f + expf(-__ldg(pr + 0)));
    float b1 = 0.01f + (5.0f  - 0.01f) / (1.0f + expf(-__ldg(pr + 1)));
    float a2 = 0.5f  + (13.0f - 0.5f)  / (1.0f + expf(-__ldg(pr + 2)));
    float b2 = 0.15f + (1.5f  - 0.15f) / (1.0f + expf(-__ldg(pr + 3)));

    unsigned long long uhp[CH];
    {
        const float L2E = 1.44269504f;
        float i1 = L2E / b1, i2 = L2E / b2;
        float w1[CH], w2[CH];
        float n1 = 0.f, n2 = 0.f;
#pragma unroll
        for (int l = 0; l < CH; l++) {
            float t  = (float)l + 0.5f;
            float lt = lg2a(t);
            w1[l] = ex2a(fmaf(a1 - 1.0f, lt, -t * i1));
            w2[l] = ex2a(fmaf(a2 - 1.0f, lt, -t * i2));
            n1 += w1[l]; n2 += w2[l];
        }
        n1 = 1.0f / n1; n2 = 1.0f / n2;
#pragma unroll
        for (int l = 0; l < CH; l++) PACK2(uhp[l], w1[l] * n1, w2[l] * n2);
    }

    // ring preload: slot j holds h[t0 - 15 + j]
    unsigned long long hpk[CH];
    hpk[0] = 0ull;
#pragma unroll
    for (int j = 1; j < CH; j++) {
        int t = t0 - CH + j;
        if (t >= 0) {
            float4 h = __ldg(&g_scr[(size_t)t * GG + g]);
            PACK2(hpk[j], h.x, h.y);
        } else hpk[j] = 0ull;
    }

#pragma unroll 1
    for (int cb = 0; cb < SLEN / CH; cb++) {
        const int tb = t0 + cb * CH;
        if (tb >= TT) break;

        // batch-load 15 history rows (MLP=15)
        float4 hv[CH];
#pragma unroll
        for (int u = 0; u < CH; u++) {
            int t = tb + u;
            hv[u] = (t < TT) ? __ldg(&g_scr[(size_t)t * GG + g])
                             : make_float4(0.f, 0.f, 0.f, 0.f);
        }
#pragma unroll
        for (int u = 0; u < CH; u++) {
            PACK2(hpk[u], hv[u].x, hv[u].y);
            unsigned long long qp = 0ull;
#pragma unroll
            for (int l = 0; l < CH; l++)
                FMA2(qp, uhp[l], hpk[(u - l + CH) % CH], qp);
            float qlo, qhi;
            UNPACK2(qlo, qhi, qp);
            if (tb + u < TT)
                out[(size_t)(tb + u) * GG + g] = hv[u].z + qlo + qhi;
        }
    }
}

extern "C" void kernel_launch(void* const* d_in, const int* in_sizes, int n_in,
                              void* d_out, int out_size)
{
    (void)in_sizes; (void)n_in; (void)out_size;
    const float* x   = (const float*)d_in[0];   // x_phy  [1460, 5000, 3]
    const float* par = (const float*)d_in[1];   // params [1460, 5000, 20]
    float* out = (float*)d_out;                 // Q      [1460, 5000]

    hmets_scan<<<(GG + CPB - 1) / CPB, WPB * 32>>>(x, par);
    dim3 cg((GG + 31) / 32, NSL);
    hmets_conv<<<cg, 32>>>(par, out);
}

// round 13
// speedup vs baseline: 2.7597x; 1.0626x over previous
#include <cuda_runtime.h>
#include <math.h>

#define TT   1460
#define TTP  1470            // padded scratch time (49 * 30)
#define GG   5000
#define TS   30              // timesteps per smem tile
#define NT   49              // 1470 / 30
#define CH   15              // UH length
#define CPW  4               // cells per warp (lanes 4-31 duplicate lane&3)
#define WPB  4               // warps per block -> one per SMSP
#define CPB  16              // cells per block
#define RW   12              // floats per row per warp (CPW * 3)
#define NSL  14              // conv t-slices
#define SLEN 105             // steps per conv slice (7 * 15)

// scratch: (ht0, ht1) per (t, g), time-padded -- 58.8 MB
__device__ float2 g_scr[(size_t)TTP * GG];

// ---- packed f32x2 + approx transcendental helpers -----------------------------
#define PACK2(d, lo, hi)   asm("mov.b64 %0, {%1, %2};" : "=l"(d) : "f"(lo), "f"(hi))
#define UNPACK2(lo, hi, d) asm("mov.b64 {%0, %1}, %2;" : "=f"(lo), "=f"(hi) : "l"(d))
#define FMA2(d, a, b, c)   asm("fma.rn.f32x2 %0, %1, %2, %3;" : "=l"(d) : "l"(a), "l"(b), "l"(c))

__device__ __forceinline__ float lg2a(float x) { float r; asm("lg2.approx.f32 %0, %1;" : "=f"(r) : "f"(x)); return r; }
__device__ __forceinline__ float ex2a(float x) { float r; asm("ex2.approx.f32 %0, %1;" : "=f"(r) : "f"(x)); return r; }

__device__ __forceinline__ void cp_async16(void* sm, const void* gm) {
    unsigned a = (unsigned)__cvta_generic_to_shared(sm);
    asm volatile("cp.async.cg.shared.global [%0], [%1], 16;\n" :: "r"(a), "l"(gm));
}
__device__ __forceinline__ void cp_commit() { asm volatile("cp.async.commit_group;\n" ::: "memory"); }
__device__ __forceinline__ void cp_wait1()  { asm volatile("cp.async.wait_group 1;\n" ::: "memory"); }
__device__ __forceinline__ void cp_wait0()  { asm volatile("cp.async.wait_group 0;\n" ::: "memory"); }

// ============== Kernel A: warp-spread scan (spine only) =========================
__global__ __launch_bounds__(128, 1)
void hmets_scan(const float* __restrict__ x,
                const float* __restrict__ par,
                float* __restrict__ out)
{
    __shared__ __align__(16) float smAll[WPB][2][TS * RW];   // 11520 B

    const int tid  = threadIdx.x;
    const int wid  = tid >> 5;
    const int lane = tid & 31;
    const int li   = lane & 3;                    // cell slot within warp
    const int gw0  = blockIdx.x * CPB + wid * CPW;
    const bool wact = (gw0 < GG);                 // GG % CPW == 0
    const int g    = gw0 + li;

    float (*smw)[TS * RW] = smAll[wid];

    // -------- per-cell physical parameters (last timestep row only) -----------------
    const int gcl = wact ? (g < GG ? g : GG - 1) : 0;
    const float* pr = par + ((size_t)(TT - 1) * GG + gcl) * 20;
    float s[16];
#pragma unroll
    for (int i = 0; i < 16; i++) {
        float v = __ldg(pr + i);
        s[i] = 1.0f / (1.0f + expf(-v));
    }
    const float ddf_min = 20.0f * s[0];
    const float ddf_sum = ddf_min + 20.0f * s[1];
    const float Tbm     = -2.0f + 5.0f * s[2];
    const float Kcum    = 0.01f + 0.19f * s[3];
    const float fcmin   = 0.1f * s[4];
    const float fc_sum  = fcmin + 0.01f + 0.24f * s[5];
    const float Ccum    = 0.005f + 0.045f * s[6];
    const float Tbf     = -5.0f + 7.0f * s[7];
    const float Kf      = 5.0f * s[8];
    const float efe     = s[9];
    const float ETe     = 3.0f * s[10];
    const float cRun    = s[11];
    const float cV2P    = 1e-5f + (0.02f - 1e-5f) * s[12];
    const float cVad    = 0.1f * s[13];
    const float cPh     = 1e-5f + (0.01f - 1e-5f) * s[14];
    const float Vmax    = 0.001f + (500.0f - 0.001f) * s[15];
    const float invVmax = 1.0f / Vmax;
    const float dmK   = ddf_min * Kcum;       // ddf = fma(dmK, C, ddf_min)
    const float fcC   = fc_sum * Ccum;        // wrf = fma(-fcC, C, fc_sum)
    const float cVb   = 1.0f - cVad - cV2P;   // V1 = fma(cVb, V, infil) - ht1
    const float lKf   = lg2a(Kf);             // potf = ex2(fma(efe, lg2(base), lKf))
    const float omPh  = 1.0f - cPh;           // P' = (P + v2p) * (1 - cPh)

    // -------- per-warp tile prefetch (cp.async, zero-padded) ------------------------
    auto prefetch = [&](int k) {
        float* dst = smw[k & 1];
        int t0 = k * TS;
        for (int j = lane; j < TS * 3; j += 32) {      // 3 float4 per row
            int row = j / 3, c = j - row * 3;
            if (wact && (t0 + row) < TT) {
                const float* gp = x + (size_t)(t0 + row) * (GG * 3) + gw0 * 3 + c * 4;
                cp_async16(dst + row * RW + c * 4, gp);
            } else {
                float4 z = {0.f, 0.f, 0.f, 0.f};
                *(float4*)(dst + row * RW + c * 4) = z;
            }
        }
        cp_commit();
    };

    // -------- state -----------------------------------------------------------------
    float S = 1e-5f, W = 1e-5f, C = 1e-5f, P = 1e-5f;
    float V = 0.5f * Vmax;

    const bool wr_act = wact && (lane < CPW);
    float2* sp = g_scr + g;       // advances by GG per step (padded time, no guard)
    float*  op = out + g;

    prefetch(0);
    for (int k = 0; k < NT; k++) {
        const int t0 = k * TS;
        if (k + 1 < NT) { prefetch(k + 1); cp_wait1(); }
        else            { cp_wait0(); }
        __syncwarp();
        const float* sb = smw[k & 1];

#pragma unroll 1
        for (int c2 = 0; c2 < 2; c2++) {
            const float* rb = sb + c2 * CH * RW + li * 3;
            const int tb = t0 + c2 * CH;
#pragma unroll
            for (int u = 0; u < CH; u++) {
                float Pp = rb[u * RW + 0];
                float Tt = rb[u * RW + 1];
                float PE = rb[u * RW + 2];

                // forcing-derived (off the state recurrence)
                float rain = (Tt >= 0.0f) ? Pp : 0.0f;
                float snow = Pp - rain;
                float base = fmaxf(Tbf - Tt, 1e-5f);
                float potf = ex2a(fmaf(efe, lg2a(base), lKf));
                float dtp  = fmaxf(Tt - Tbm, 0.0f);
                float RET  = ETe * PE;

                // snowpack
                float fr = fminf(potf, W);
                W -= fr;
                S += fr;
                float ddf  = fminf(fmaf(dmK, C, ddf_min), ddf_sum);
                float S1   = S + snow;
                float melt = fminf(ddf * dtp, S1);
                S = S1 - melt;
                float Ct = C + melt;
                C = (S > 1e-5f) ? Ct : 0.0f;

                // retention (select -> min identity, exact)
                float wrf  = fmaxf(fmaf(-fcC, C, fc_sum), fcmin);
                float wr   = wrf * S;
                float wtmp = (W + rain) + melt;
                float wa   = fmaxf(wtmp - wr, 0.0f);
                W = fminf(wtmp, wr);

                // vadose / phreatic (overflow clamp -> min identity, exact)
                float ratio = V * invVmax;
                float cr    = cRun * ratio;
                float cr2   = cr * ratio;
                float ht0   = cr * wa;
                float infil = fmaxf((wa - RET) - ht0, 0.0f);
                float ht1   = cr2 * infil;
                float v2p   = cV2P * V;
                float V1    = fmaf(cVb, V, infil) - ht1;
                float Vn    = fminf(V1, Vmax);
                float gwV   = fmaf(cVad, V, 0.0f);   // ht2 from OLD V
                V = Vn;
                ht1 += V1 - Vn;
                float Pp1 = P + v2p;
                float ht3 = cPh * Pp1;
                P = Pp1 * omPh;
                float gw  = gwV + ht3;

                // stores: scratch unguarded in time (padded), out guarded
                float2 h2; h2.x = ht0; h2.y = ht1;
                if (wr_act) *sp = h2;
                sp += GG;
                if (wr_act && (tb + u) < TT) *op = gw;
                op += GG;
            }
        }
        __syncwarp();
    }
}

// ============== Kernel B: dual gamma-UH conv (RMW into out) =====================
__global__ __launch_bounds__(32, 16)
void hmets_conv(const float* __restrict__ par,
                float* __restrict__ out)
{
    const int lane = threadIdx.x;
    const int g    = blockIdx.x * 32 + lane;
    if (g >= GG) return;
    const int t0   = blockIdx.y * SLEN;

    // routing params (sigmoid of last row, cols 16..19)
    const float* pr = par + ((size_t)(TT - 1) * GG + g) * 20 + 16;
    float a1 = 0.3f  + (20.0f - 0.3f)  / (1.0f + expf(-__ldg(pr + 0)));
    float b1 = 0.01f + (5.0f  - 0.01f) / (1.0f + expf(-__ldg(pr + 1)));
    float a2 = 0.5f  + (13.0f - 0.5f)  / (1.0f + expf(-__ldg(pr + 2)));
    float b2 = 0.15f + (1.5f  - 0.15f) / (1.0f + expf(-__ldg(pr + 3)));

    unsigned long long uhp[CH];
    {
        const float L2E = 1.44269504f;
        float i1 = L2E / b1, i2 = L2E / b2;
        float w1[CH], w2[CH];
        float n1 = 0.f, n2 = 0.f;
#pragma unroll
        for (int l = 0; l < CH; l++) {
            float t  = (float)l + 0.5f;
            float lt = lg2a(t);
            w1[l] = ex2a(fmaf(a1 - 1.0f, lt, -t * i1));
            w2[l] = ex2a(fmaf(a2 - 1.0f, lt, -t * i2));
            n1 += w1[l]; n2 += w2[l];
        }
        n1 = 1.0f / n1; n2 = 1.0f / n2;
#pragma unroll
        for (int l = 0; l < CH; l++) PACK2(uhp[l], w1[l] * n1, w2[l] * n2);
    }

    // ring preload: slot j holds h[t0 - 15 + j]
    unsigned long long hpk[CH];
    hpk[0] = 0ull;
#pragma unroll
    for (int j = 1; j < CH; j++) {
        int t = t0 - CH + j;
        if (t >= 0) {
            float2 h = __ldg(&g_scr[(size_t)t * GG + g]);
            PACK2(hpk[j], h.x, h.y);
        } else hpk[j] = 0ull;
    }

#pragma unroll 1
    for (int cb = 0; cb < SLEN / CH; cb++) {
        const int tb = t0 + cb * CH;
        if (tb >= TT) break;

        // batch-load 15 history rows + 15 gw partials (MLP)
        float2 hv[CH];
        float  gv[CH];
#pragma unroll
        for (int u = 0; u < CH; u++) {
            int t = tb + u;
            if (t < TT) {
                hv[u] = __ldg(&g_scr[(size_t)t * GG + g]);
                gv[u] = out[(size_t)t * GG + g];
            } else {
                hv[u] = make_float2(0.f, 0.f);
                gv[u] = 0.f;
            }
        }
#pragma unroll
        for (int u = 0; u < CH; u++) {
            PACK2(hpk[u], hv[u].x, hv[u].y);
            unsigned long long qp = 0ull;
#pragma unroll
            for (int l = 0; l < CH; l++)
                FMA2(qp, uhp[l], hpk[(u - l + CH) % CH], qp);
            float qlo, qhi;
            UNPACK2(qlo, qhi, qp);
            if (tb + u < TT)
                out[(size_t)(tb + u) * GG + g] = gv[u] + qlo + qhi;
        }
    }
}

extern "C" void kernel_launch(void* const* d_in, const int* in_sizes, int n_in,
                              void* d_out, int out_size)
{
    (void)in_sizes; (void)n_in; (void)out_size;
    const float* x   = (const float*)d_in[0];   // x_phy  [1460, 5000, 3]
    const float* par = (const float*)d_in[1];   // params [1460, 5000, 20]
    float* out = (float*)d_out;                 // Q      [1460, 5000]

    hmets_scan<<<(GG + CPB - 1) / CPB, WPB * 32>>>(x, par, out);
    dim3 cg((GG + 31) / 32, NSL);
    hmets_conv<<<cg, 32>>>(par, out);
}